// round 2
// baseline (speedup 1.0000x reference)
#include <cuda_runtime.h>
#include <math.h>

#define BATCH 8
#define SEQ   1024
#define DEMB  1024
#define NHEAD 16
#define DHEAD 64
#define MROWS (BATCH*SEQ)   // 8192

// Scratch (allocation-free rule: device globals)
__device__ float g_Q[(size_t)BATCH*NHEAD*SEQ*DHEAD];
__device__ float g_K[(size_t)BATCH*NHEAD*SEQ*DHEAD];
__device__ float g_V[(size_t)BATCH*NHEAD*SEQ*DHEAD];
__device__ float g_O[(size_t)MROWS*DEMB];

// ---------------------------------------------------------------------------
// QKV GEMM: X[8192,1024] @ Wqkv[1024,3072] + b_qkv
// Epilogue scatters into Q/K/V with layout [B,H,N,64].
// qkv packing: col c -> h = c/192, dd = (c%192)/3, which = c%3
// ---------------------------------------------------------------------------
__global__ __launch_bounds__(256) void qkv_gemm_kernel(
    const float* __restrict__ X, const float* __restrict__ W,
    const float* __restrict__ bias)
{
    __shared__ float As[16][128];
    __shared__ float Bs[16][128];
    const int bm  = blockIdx.y * 128;
    const int bn  = blockIdx.x * 128;
    const int tid = threadIdx.x;
    const int tx  = tid & 15;
    const int ty  = tid >> 4;

    float acc[8][8];
    #pragma unroll
    for (int i = 0; i < 8; i++)
        #pragma unroll
        for (int j = 0; j < 8; j++) acc[i][j] = 0.f;

    for (int k0 = 0; k0 < 1024; k0 += 16) {
        #pragma unroll
        for (int i = 0; i < 2; i++) {
            int f   = tid + i * 256;
            int row = f >> 2;
            int c4  = (f & 3) << 2;
            float4 v = *(const float4*)(X + (size_t)(bm + row) * 1024 + k0 + c4);
            As[c4 + 0][row] = v.x; As[c4 + 1][row] = v.y;
            As[c4 + 2][row] = v.z; As[c4 + 3][row] = v.w;
        }
        #pragma unroll
        for (int i = 0; i < 2; i++) {
            int f   = tid + i * 256;
            int row = f >> 5;
            int col = (f & 31) << 2;
            *(float4*)(&Bs[row][col]) =
                *(const float4*)(W + (size_t)(k0 + row) * 3072 + bn + col);
        }
        __syncthreads();
        #pragma unroll
        for (int k = 0; k < 16; k++) {
            float a[8], b[8];
            *(float4*)(a)     = *(const float4*)(&As[k][ty * 4]);
            *(float4*)(a + 4) = *(const float4*)(&As[k][ty * 4 + 64]);
            *(float4*)(b)     = *(const float4*)(&Bs[k][tx * 4]);
            *(float4*)(b + 4) = *(const float4*)(&Bs[k][tx * 4 + 64]);
            #pragma unroll
            for (int i = 0; i < 8; i++)
                #pragma unroll
                for (int j = 0; j < 8; j++)
                    acc[i][j] += a[i] * b[j];
        }
        __syncthreads();
    }

    #pragma unroll
    for (int i = 0; i < 8; i++) {
        int gr = bm + ty * 4 + ((i & 4) << 4) + (i & 3);   // global row (b*1024+n)
        int bb = gr >> 10;
        int nn = gr & 1023;
        #pragma unroll
        for (int j = 0; j < 8; j++) {
            int gc = bn + tx * 4 + ((j & 4) << 4) + (j & 3); // global col in [0,3072)
            float v = acc[i][j] + bias[gc];
            int h  = gc / 192;
            int r  = gc - h * 192;
            int dd = r / 3;
            int which = r - dd * 3;
            size_t idx = (((size_t)(bb * NHEAD + h)) * SEQ + nn) * DHEAD + dd;
            if      (which == 0) g_Q[idx] = v;
            else if (which == 1) g_K[idx] = v;
            else                 g_V[idx] = v;
        }
    }
}

// ---------------------------------------------------------------------------
// Flash attention (fp32, online softmax). 1 block = 128 queries of one (b,h).
// score = q.k (NO 1/sqrt(d) inside softmax); final scale = 1/(32 * l).
// Writes O as [B*N, D] with column = h*64 + dd.
// ---------------------------------------------------------------------------
__global__ __launch_bounds__(128) void flash_attn_kernel()
{
    const int bh   = blockIdx.x;       // 0..127
    const int qt   = blockIdx.y;       // 0..7
    const int tid  = threadIdx.x;
    const int qrow = qt * 128 + tid;

    const float* __restrict__ Qb = g_Q + (size_t)bh * SEQ * DHEAD;
    const float* __restrict__ Kb = g_K + (size_t)bh * SEQ * DHEAD;
    const float* __restrict__ Vb = g_V + (size_t)bh * SEQ * DHEAD;

    float q[64];
    {
        const float4* qp = (const float4*)(Qb + (size_t)qrow * DHEAD);
        #pragma unroll
        for (int c = 0; c < 16; c++) {
            float4 t = qp[c];
            q[4*c] = t.x; q[4*c+1] = t.y; q[4*c+2] = t.z; q[4*c+3] = t.w;
        }
    }

    float o[64];
    #pragma unroll
    for (int i = 0; i < 64; i++) o[i] = 0.f;
    float m = -1e30f, l = 0.f;

    __shared__ float Ks[16][64];
    __shared__ float Vs[16][64];

    for (int t = 0; t < SEQ / 16; t++) {
        __syncthreads();
        {
            const float4* kg = (const float4*)(Kb + (size_t)t * 16 * DHEAD);
            const float4* vg = (const float4*)(Vb + (size_t)t * 16 * DHEAD);
            float4* ks = (float4*)(&Ks[0][0]);
            float4* vs = (float4*)(&Vs[0][0]);
            ks[tid]       = kg[tid];
            ks[tid + 128] = kg[tid + 128];
            vs[tid]       = vg[tid];
            vs[tid + 128] = vg[tid + 128];
        }
        __syncthreads();

        float s[16];
        #pragma unroll
        for (int j = 0; j < 16; j++) {
            float s0 = 0.f, s1 = 0.f, s2 = 0.f, s3 = 0.f;
            const float4* kr = (const float4*)(&Ks[j][0]);
            #pragma unroll
            for (int c = 0; c < 16; c++) {
                float4 kv = kr[c];
                s0 += q[4*c]     * kv.x;
                s1 += q[4*c + 1] * kv.y;
                s2 += q[4*c + 2] * kv.z;
                s3 += q[4*c + 3] * kv.w;
            }
            s[j] = (s0 + s1) + (s2 + s3);
        }

        float tmax = s[0];
        #pragma unroll
        for (int j = 1; j < 16; j++) tmax = fmaxf(tmax, s[j]);
        float nm    = fmaxf(m, tmax);
        float alpha = __expf(m - nm);
        float psum  = 0.f;
        #pragma unroll
        for (int j = 0; j < 16; j++) { s[j] = __expf(s[j] - nm); psum += s[j]; }
        l = l * alpha + psum;
        m = nm;

        #pragma unroll
        for (int dd = 0; dd < 64; dd++) o[dd] *= alpha;
        #pragma unroll
        for (int j = 0; j < 16; j++) {
            float pj = s[j];
            const float4* vr = (const float4*)(&Vs[j][0]);
            #pragma unroll
            for (int c = 0; c < 16; c++) {
                float4 vv = vr[c];
                o[4*c]     += pj * vv.x;
                o[4*c + 1] += pj * vv.y;
                o[4*c + 2] += pj * vv.z;
                o[4*c + 3] += pj * vv.w;
            }
        }
    }

    // att = softmax/32  ->  out = (1/32) * (o / l)
    const float inv = 1.0f / (l * 32.0f);
    const int bb = bh >> 4;
    const int hh = bh & 15;
    float4* op = (float4*)(g_O + ((size_t)(bb * SEQ + qrow)) * DEMB + hh * DHEAD);
    #pragma unroll
    for (int c = 0; c < 16; c++)
        op[c] = make_float4(o[4*c] * inv, o[4*c+1] * inv, o[4*c+2] * inv, o[4*c+3] * inv);
}

// ---------------------------------------------------------------------------
// Proj GEMM: O[8192,1024] @ Wproj[1024,1024] + b_proj -> d_out
// ---------------------------------------------------------------------------
__global__ __launch_bounds__(256) void proj_gemm_kernel(
    const float* __restrict__ W, const float* __restrict__ bias,
    float* __restrict__ out)
{
    __shared__ float As[16][128];
    __shared__ float Bs[16][128];
    const int bm  = blockIdx.y * 128;
    const int bn  = blockIdx.x * 128;
    const int tid = threadIdx.x;
    const int tx  = tid & 15;
    const int ty  = tid >> 4;

    float acc[8][8];
    #pragma unroll
    for (int i = 0; i < 8; i++)
        #pragma unroll
        for (int j = 0; j < 8; j++) acc[i][j] = 0.f;

    for (int k0 = 0; k0 < 1024; k0 += 16) {
        #pragma unroll
        for (int i = 0; i < 2; i++) {
            int f   = tid + i * 256;
            int row = f >> 2;
            int c4  = (f & 3) << 2;
            float4 v = *(const float4*)(g_O + (size_t)(bm + row) * 1024 + k0 + c4);
            As[c4 + 0][row] = v.x; As[c4 + 1][row] = v.y;
            As[c4 + 2][row] = v.z; As[c4 + 3][row] = v.w;
        }
        #pragma unroll
        for (int i = 0; i < 2; i++) {
            int f   = tid + i * 256;
            int row = f >> 5;
            int col = (f & 31) << 2;
            *(float4*)(&Bs[row][col]) =
                *(const float4*)(W + (size_t)(k0 + row) * 1024 + bn + col);
        }
        __syncthreads();
        #pragma unroll
        for (int k = 0; k < 16; k++) {
            float a[8], b[8];
            *(float4*)(a)     = *(const float4*)(&As[k][ty * 4]);
            *(float4*)(a + 4) = *(const float4*)(&As[k][ty * 4 + 64]);
            *(float4*)(b)     = *(const float4*)(&Bs[k][tx * 4]);
            *(float4*)(b + 4) = *(const float4*)(&Bs[k][tx * 4 + 64]);
            #pragma unroll
            for (int i = 0; i < 8; i++)
                #pragma unroll
                for (int j = 0; j < 8; j++)
                    acc[i][j] += a[i] * b[j];
        }
        __syncthreads();
    }

    #pragma unroll
    for (int i = 0; i < 8; i++) {
        int gr = bm + ty * 4 + ((i & 4) << 4) + (i & 3);
        #pragma unroll
        for (int j = 0; j < 8; j++) {
            int gc = bn + tx * 4 + ((j & 4) << 4) + (j & 3);
            out[(size_t)gr * 1024 + gc] = acc[i][j] + bias[gc];
        }
    }
}

// ---------------------------------------------------------------------------
extern "C" void kernel_launch(void* const* d_in, const int* in_sizes, int n_in,
                              void* d_out, int out_size)
{
    const float* x      = (const float*)d_in[0];
    const float* w_qkv  = (const float*)d_in[1];
    const float* b_qkv  = (const float*)d_in[2];
    const float* w_proj = (const float*)d_in[3];
    const float* b_proj = (const float*)d_in[4];
    float* out = (float*)d_out;

    dim3 g1(3072 / 128, MROWS / 128);   // 24 x 64
    qkv_gemm_kernel<<<g1, 256>>>(x, w_qkv, b_qkv);

    dim3 g2(BATCH * NHEAD, SEQ / 128);  // 128 x 8
    flash_attn_kernel<<<g2, 128>>>();

    dim3 g3(1024 / 128, MROWS / 128);   // 8 x 64
    proj_gemm_kernel<<<g3, 256>>>(w_proj, b_proj, out);
}